// round 9
// baseline (speedup 1.0000x reference)
#include <cuda_runtime.h>
#include <cstdint>

// Problem shape (fixed by the dataset)
#define BB 8
#define SS 128
#define RR 192
#define CC 192
#define NX (CC / 4)   // 48 float4 segments per row

#define RTILES (RR / 4)                // 48
#define STILES (SS / 2)                // 64
#define NTILES (BB * STILES * RTILES)  // 24576
#define NBLOCKS 888                    // 148 SMs * 6 resident CTAs

// SPACING = (2.0, 1.5, 1.5) along (S, R, C)
#define INV2DX 0.25f
#define INV2DY 0.33333333333333333f
#define INV2DZ 0.33333333333333333f
#define INVDX2 0.25f
#define INVDY2 0.44444444444444444f
#define INVDZ2 0.44444444444444444f

typedef unsigned long long ull;

__device__ __forceinline__ int clamp_i(int v, int lo, int hi) {
    return min(max(v, lo), hi);
}

// ---- packed f32x2 helpers ----
__device__ __forceinline__ ull f2fma(ull a, ull b, ull c) {
    ull r; asm("fma.rn.f32x2 %0, %1, %2, %3;" : "=l"(r) : "l"(a), "l"(b), "l"(c)); return r;
}
__device__ __forceinline__ ull f2mul(ull a, ull b) {
    ull r; asm("mul.rn.f32x2 %0, %1, %2;" : "=l"(r) : "l"(a), "l"(b)); return r;
}
__device__ __forceinline__ ull f2add(ull a, ull b) {
    ull r; asm("add.rn.f32x2 %0, %1, %2;" : "=l"(r) : "l"(a), "l"(b)); return r;
}
// register-pair pack/unpack (mov.b64 idiom — no integer ALU chain)
__device__ __forceinline__ ull packf2(float lo, float hi) {
    ull r; asm("mov.b64 %0, {%1, %2};" : "=l"(r) : "f"(lo), "f"(hi)); return r;
}
__device__ __forceinline__ void unpackf2(ull v, float& lo, float& hi) {
    asm("mov.b64 {%0, %1}, %2;" : "=f"(lo), "=f"(hi) : "l"(v));
}

struct PkC {   // packed constants
    ull NEG1;  // (-1, -1)
    ull A2;    // 1/16   : gx^2 scale  (1/(2*2.0))^2
    ull B2;    // 1/9    : gy^2, gz^2 scale
    ull CX;    // -1/4   : -(1/dx^2)
    ull CYZ;   // -4/9   : -(1/dy^2) = -(1/dz^2)
    ull KP;    // +2*(1/4 + 4/9 + 4/9) = +2.2777...  (for G' = -G)
    ull NH;    // -0.5
};

// One output (2 packed f32x2) for one plane.
// c,xm,xp,ym,yp,d : ulonglong2 views of the float4 rows.
// left/right: z-edge scalars (values unused on lo/hi lanes; patched).
__device__ __forceinline__ ulonglong2 plane_out_pk(
    const ulonglong2 c,
    const ulonglong2 xm, const ulonglong2 xp,
    const ulonglong2 ym, const ulonglong2 yp,
    const float left, const float right,
    const ulonglong2 d,
    const bool lo, const bool hi,
    const PkC& K)
{
    float c0, c1, c2, c3;
    unpackf2(c.x, c0, c1);
    unpackf2(c.y, c2, c3);
    const ull zm0  = packf2(left, c0);   // zm for comps 0,1
    const ull zmid = packf2(c1, c2);     // zm for comps 2,3 AND zp for comps 0,1
    const ull zp1  = packf2(c3, right);  // zp for comps 2,3

    // F = dx^2/16 + dy^2/9 + dz^2/9
    ull t, F0, F1;
    t = f2fma(xm.x, K.NEG1, xp.x); F0 = f2mul(f2mul(t, t), K.A2);
    t = f2fma(ym.x, K.NEG1, yp.x); F0 = f2fma(f2mul(t, t), K.B2, F0);
    t = f2fma(zm0,  K.NEG1, zmid); F0 = f2fma(f2mul(t, t), K.B2, F0);
    t = f2fma(xm.y, K.NEG1, xp.y); F1 = f2mul(f2mul(t, t), K.A2);
    t = f2fma(ym.y, K.NEG1, yp.y); F1 = f2fma(f2mul(t, t), K.B2, F1);
    t = f2fma(zmid, K.NEG1, zp1);  F1 = f2fma(f2mul(t, t), K.B2, F1);

    // G' = -G = (xp+xm)*CX + (yp+ym)*CYZ + (zp+zm)*CYZ + KP*c
    ull G0 = f2mul(c.x, K.KP);
    G0 = f2fma(f2add(xp.x, xm.x), K.CX,  G0);
    G0 = f2fma(f2add(yp.x, ym.x), K.CYZ, G0);
    G0 = f2fma(f2add(zmid, zm0),  K.CYZ, G0);
    ull G1 = f2mul(c.y, K.KP);
    G1 = f2fma(f2add(xp.y, xm.y), K.CX,  G1);
    G1 = f2fma(f2add(yp.y, ym.y), K.CYZ, G1);
    G1 = f2fma(f2add(zp1,  zmid), K.CYZ, G1);

    // o = -0.5*F - d*G = fma(F, -0.5, d*G')
    ulonglong2 o;
    o.x = f2fma(F0, K.NH, f2mul(d.x, G0));
    o.y = f2fma(F1, K.NH, f2mul(d.y, G1));

    if (lo) {
        // patch comps 0,1 (columns k=0,1)
        float xm1q, xp1q, ym1q, yp1q, d0f, d1f, dum;
        unpackf2(xm.x, dum, xm1q);
        unpackf2(xp.x, dum, xp1q);
        unpackf2(ym.x, dum, ym1q);
        unpackf2(yp.x, dum, yp1q);
        unpackf2(d.x, d0f, d1f);
        const float gx1 = (xp1q - xm1q) * INV2DX;
        const float gy1 = (yp1q - ym1q) * INV2DY;
        const float Fxy1 = gx1 * gx1 + gy1 * gy1;
        const float Gxy1 = (xp1q - 2.0f * c1 + xm1q) * INVDX2
                         + (yp1q - 2.0f * c1 + ym1q) * INVDY2;
        // k=1: zm tap is Q(0)=P[col 1]=c1
        const float gz1 = (c2 - c1) * INV2DZ;
        const float Gz1 = (c2 - c1) * INVDZ2;
        const float o1f = -0.5f * (Fxy1 + gz1 * gz1) - d1f * (Gxy1 + Gz1);
        // k=0: all column taps clamp to col 1; gz=0, Gz=0
        const float o0f = -0.5f * Fxy1 - d0f * Gxy1;
        o.x = packf2(o0f, o1f);
    }
    if (hi) {
        // patch comps 2,3 (columns k=190,191)
        float xm2q, xp2q, ym2q, yp2q, d2f, d3f, dum;
        unpackf2(xm.y, xm2q, dum);
        unpackf2(xp.y, xp2q, dum);
        unpackf2(ym.y, ym2q, dum);
        unpackf2(yp.y, yp2q, dum);
        unpackf2(d.y, d2f, d3f);
        const float gx2 = (xp2q - xm2q) * INV2DX;
        const float gy2 = (yp2q - ym2q) * INV2DY;
        const float Fxy2 = gx2 * gx2 + gy2 * gy2;
        const float Gxy2 = (xp2q - 2.0f * c2 + xm2q) * INVDX2
                         + (yp2q - 2.0f * c2 + ym2q) * INVDY2;
        // k=190: zp tap is Q(191)=P[col 190]=c2
        const float gz2 = (c2 - c1) * INV2DZ;
        const float Gz2 = (c1 - c2) * INVDZ2;
        const float o2f = -0.5f * (Fxy2 + gz2 * gz2) - d2f * (Gxy2 + Gz2);
        // k=191: all column taps clamp to col 190; gz=0, Gz=0
        const float o3f = -0.5f * Fxy2 - d3f * Gxy2;
        o.y = packf2(o2f, o3f);
    }

    return o;
}

__global__ __launch_bounds__(192, 6)
void flowp_kernel_pk2(const float* __restrict__ P,
                      const float* __restrict__ D,
                      float* __restrict__ out)
{
    const int tx = threadIdx.x;          // 0..47 : float4 index along C
    const int ty = threadIdx.y;          // 0..3  : r within tile
    const int k0 = tx * 4;
    const bool lo = (tx == 0);
    const bool hi = (tx == NX - 1);

    const int kl = lo ? k0 : k0 - 1;
    const int kr = hi ? CC - 1 : k0 + 4;

    PkC K;
    K.NEG1 = packf2(-1.0f, -1.0f);
    K.A2   = packf2(0.0625f, 0.0625f);
    K.B2   = packf2(0.11111111111111111f, 0.11111111111111111f);
    K.CX   = packf2(-0.25f, -0.25f);
    K.CYZ  = packf2(-0.44444444444444444f, -0.44444444444444444f);
    K.KP   = packf2(2.2777777777777777f, 2.2777777777777777f);
    K.NH   = packf2(-0.5f, -0.5f);

    for (int T = blockIdx.x; T < NTILES; T += NBLOCKS) {
        const int rb   = T % RTILES;
        const int rest = T / RTILES;
        const int st   = rest & (STILES - 1);
        const int b    = rest >> 6;          // / STILES (=64)

        const int r  = rb * 4 + ty;
        const int s0 = st * 2;

        const int i0 = clamp_i(s0 - 1, 1, SS - 2);
        const int i1 = clamp_i(s0,     1, SS - 2);
        const int i2 = clamp_i(s0 + 1, 1, SS - 2);
        const int i3 = clamp_i(s0 + 2, 1, SS - 2);

        const int cr = clamp_i(r,     1, RR - 2);
        const int rm = clamp_i(r - 1, 1, RR - 2);
        const int rp = clamp_i(r + 1, 1, RR - 2);

        const long long base = (long long)b * (SS * RR * CC);
        const float* Pb = P + base;

        const int rowA   = (i0 * RR + cr) * CC;
        const int rowC1  = (i1 * RR + cr) * CC;
        const int rowC2  = (i2 * RR + cr) * CC;
        const int rowBp  = (i3 * RR + cr) * CC;
        const int rowY1m = (i1 * RR + rm) * CC;
        const int rowY1p = (i1 * RR + rp) * CC;
        const int rowY2m = (i2 * RR + rm) * CC;
        const int rowY2p = (i2 * RR + rp) * CC;

        // Vector loads as packed pairs (float4 == 2 x f32x2, 16B aligned)
        const ulonglong2 A   = __ldg((const ulonglong2*)(Pb + rowA   + k0));
        const ulonglong2 C1  = __ldg((const ulonglong2*)(Pb + rowC1  + k0));
        const ulonglong2 C2  = __ldg((const ulonglong2*)(Pb + rowC2  + k0));
        const ulonglong2 Bp  = __ldg((const ulonglong2*)(Pb + rowBp  + k0));
        const ulonglong2 Y1m = __ldg((const ulonglong2*)(Pb + rowY1m + k0));
        const ulonglong2 Y1p = __ldg((const ulonglong2*)(Pb + rowY1p + k0));
        const ulonglong2 Y2m = __ldg((const ulonglong2*)(Pb + rowY2m + k0));
        const ulonglong2 Y2p = __ldg((const ulonglong2*)(Pb + rowY2p + k0));

        const float l1 = __ldg(Pb + rowC1 + kl);
        const float r1 = __ldg(Pb + rowC1 + kr);
        const float l2 = __ldg(Pb + rowC2 + kl);
        const float r2 = __ldg(Pb + rowC2 + kr);

        const long long idx0 = base + ((long long)(s0 * RR + r)) * CC + k0;
        const long long idx1 = idx0 + (long long)RR * CC;
        const ulonglong2 d0 = __ldg((const ulonglong2*)(D + idx0));
        const ulonglong2 d1 = __ldg((const ulonglong2*)(D + idx1));

        const ulonglong2 o0 = plane_out_pk(C1, A,  C2, Y1m, Y1p, l1, r1, d0, lo, hi, K);
        const ulonglong2 o1 = plane_out_pk(C2, C1, Bp, Y2m, Y2p, l2, r2, d1, lo, hi, K);

        *((ulonglong2*)(out + idx0)) = o0;
        *((ulonglong2*)(out + idx1)) = o1;
    }
}

extern "C" void kernel_launch(void* const* d_in, const int* in_sizes, int n_in,
                              void* d_out, int out_size)
{
    // inputs (metadata order): t (unused), batch_P, D
    const float* P = (const float*)d_in[1];
    const float* D = (const float*)d_in[2];
    float* out = (float*)d_out;

    dim3 grid(NBLOCKS);
    dim3 block(NX, 4);   // 192 threads
    flowp_kernel_pk2<<<grid, block>>>(P, D, out);
}